// round 7
// baseline (speedup 1.0000x reference)
#include <cuda_runtime.h>
#include <math.h>
#include <stdint.h>

#define D_MODEL 4096
#define N_EXP   64
#define TOPK    8
#define M_CTA   64
#define TPB     256
#define KC      32
#define NCH     (D_MODEL / KC)     // 128

#define XROW    36                        // padded floats per x smem row
#define WROWF   136                       // floats per W smem row (64 (h,l) pairs + pad)
#define XTB     (M_CTA * XROW * 4)        // 9216
#define WTB     (KC * WROWF * 4)          // 17408
#define STAGE   (XTB + WTB)               // 26624
#define SMEMB   (2 * STAGE)               // 53248
#define LROW    66

// W interleaved: Wi_g[k*128 + 2e] = tf32_hi(W[e][k]), +1 = tf32(lo)
__device__ float Wi_g[D_MODEL * N_EXP * 2];

__device__ __forceinline__ float to_tf32(float x) {
    float r;
    asm("cvt.rna.tf32.f32 %0, %1;" : "=f"(r) : "f"(x));
    return r;
}

__global__ void split_W(const float* __restrict__ W)
{
    int i = blockIdx.x * 256 + threadIdx.x;   // i = k*64 + e
    if (i < N_EXP * D_MODEL) {
        int k = i >> 6, e = i & 63;
        float w = W[(size_t)e * D_MODEL + k];
        float h = to_tf32(w);
        Wi_g[(size_t)k * 128 + 2 * e]     = h;
        Wi_g[(size_t)k * 128 + 2 * e + 1] = to_tf32(w - h);
    }
}

__device__ __forceinline__ void cpa16(uint32_t dst, const void* src) {
    asm volatile("cp.async.ca.shared.global [%0], [%1], 16;\n" :: "r"(dst), "l"(src));
}
__device__ __forceinline__ void cpa_commit() { asm volatile("cp.async.commit_group;\n"); }
template <int N> __device__ __forceinline__ void cpa_wait() {
    asm volatile("cp.async.wait_group %0;\n" :: "n"(N));
}

__device__ __forceinline__ void mma_tf32(float* d, const uint32_t* a,
                                         uint32_t b0, uint32_t b1)
{
    asm volatile(
        "mma.sync.aligned.m16n8k8.row.col.f32.tf32.tf32.f32 "
        "{%0,%1,%2,%3}, {%4,%5,%6,%7}, {%8,%9}, {%0,%1,%2,%3};"
        : "+f"(d[0]), "+f"(d[1]), "+f"(d[2]), "+f"(d[3])
        : "r"(a[0]), "r"(a[1]), "r"(a[2]), "r"(a[3]), "r"(b0), "r"(b1));
}

__device__ __forceinline__ void load_stage(uint32_t sb, uint32_t sbase,
                                           const float* __restrict__ x,
                                           int blk_tok, int T, int n_tokens, int t)
{
    const int d0 = T * KC;
    // x tile: 64 rows x 128B (rows padded to 144B): 512 chunks
#pragma unroll
    for (int i = 0; i < 2; i++) {
        int c = t + i * TPB;
        int row = c >> 3, seg = c & 7;
        int tok = blk_tok + row; if (tok >= n_tokens) tok = n_tokens - 1;
        cpa16(sb + sbase + row * (XROW * 4) + seg * 16,
              x + (size_t)tok * D_MODEL + d0 + seg * 4);
    }
    // W tile: 32 rows x 512B data (rows padded to 544B): 1024 chunks
#pragma unroll
    for (int i = 0; i < 4; i++) {
        int c = t + i * TPB;
        int row = c >> 5, seg = c & 31;
        cpa16(sb + sbase + XTB + row * (WROWF * 4) + seg * 16,
              Wi_g + (size_t)(d0 + row) * 128 + seg * 4);
    }
}

__global__ void __launch_bounds__(TPB, 2)
router_kernel(const float* __restrict__ x, float* __restrict__ out,
              int n_tokens, long long out_size)
{
    extern __shared__ char smem[];
    const uint32_t sb = (uint32_t)__cvta_generic_to_shared(smem);

    const int t    = threadIdx.x;
    const int wid  = t >> 5;
    const int lane = t & 31;
    const int g    = lane >> 2;
    const int tg   = lane & 3;
    const int m0   = (wid & 3) * 16;      // warp token base (0..48)
    const int e0   = (wid >> 2) * 32;     // warp expert base (0 or 32)
    const int blk_tok = blockIdx.x * M_CTA;

    float accH[4][4], masterH[4][4], accS[4][4];
#pragma unroll
    for (int n = 0; n < 4; n++)
#pragma unroll
        for (int j = 0; j < 4; j++) {
            accH[n][j] = 0.f; masterH[n][j] = 0.f; accS[n][j] = 0.f;
        }

    load_stage(sb, 0, x, blk_tok, 0, n_tokens, t);
    cpa_commit();
    load_stage(sb, STAGE, x, blk_tok, 1, n_tokens, t);
    cpa_commit();

    for (int T = 0; T < NCH; T++) {
        const int s = T & 1;
        if (T + 1 < NCH) cpa_wait<1>(); else cpa_wait<0>();
        __syncthreads();

        const float* xs = (const float*)(smem + s * STAGE);
        const float* ws = (const float*)(smem + s * STAGE + XTB);

        const float* xr0 = xs + (m0 + g) * XROW;
        const float* xr1 = xs + (m0 + g + 8) * XROW;

#pragma unroll
        for (int ks = 0; ks < 4; ks++) {
            const int k0 = ks * 8;

            // ---- A fragment: split x into tf32 hi/lo in registers ----
            float f[4] = { xr0[k0 + tg], xr1[k0 + tg],
                           xr0[k0 + tg + 4], xr1[k0 + tg + 4] };
            uint32_t ah[4], al[4];
#pragma unroll
            for (int j = 0; j < 4; j++) {
                float h = to_tf32(f[j]);
                ah[j] = __float_as_uint(h);
                al[j] = __float_as_uint(to_tf32(f[j] - h));
            }

            // ---- B fragments: one LDS.64 yields (hi,lo) pair ----
            const float2* wr0 = (const float2*)(ws + (k0 + tg) * WROWF) + e0 + g;
            const float2* wr1 = (const float2*)(ws + (k0 + tg + 4) * WROWF) + e0 + g;
            uint32_t bh0[4], bh1[4], bl0[4], bl1[4];
#pragma unroll
            for (int n = 0; n < 4; n++) {
                float2 p0 = wr0[n * 8];
                float2 p1 = wr1[n * 8];
                bh0[n] = __float_as_uint(p0.x);
                bl0[n] = __float_as_uint(p0.y);
                bh1[n] = __float_as_uint(p1.x);
                bl1[n] = __float_as_uint(p1.y);
            }

            // hh -> accH; hl + lh -> accS
#pragma unroll
            for (int n = 0; n < 4; n++) mma_tf32(accH[n], ah, bh0[n], bh1[n]);
#pragma unroll
            for (int n = 0; n < 4; n++) mma_tf32(accS[n], ah, bl0[n], bl1[n]);
#pragma unroll
            for (int n = 0; n < 4; n++) mma_tf32(accS[n], al, bh0[n], bh1[n]);
        }

        // flush hh chunk accumulator every 8 chunks (two-level accumulation)
        if ((T & 7) == 7) {
#pragma unroll
            for (int n = 0; n < 4; n++)
#pragma unroll
                for (int j = 0; j < 4; j++) {
                    masterH[n][j] += accH[n][j];
                    accH[n][j] = 0.f;
                }
        }

        __syncthreads();
        if (T + 2 < NCH) {
            load_stage(sb, s * STAGE, x, blk_tok, T + 2, n_tokens, t);
            cpa_commit();
        }
    }

    // ---- epilogue: combine, scatter to smem logits [64][66] ----
    float* L = (float*)smem;
#pragma unroll
    for (int n = 0; n < 4; n++) {
        int col = e0 + n * 8 + 2 * tg;
        float c0 = masterH[n][0] + accS[n][0];
        float c1 = masterH[n][1] + accS[n][1];
        float c2 = masterH[n][2] + accS[n][2];
        float c3 = masterH[n][3] + accS[n][3];
        *(float2*)&L[(m0 + g) * LROW + col]     = make_float2(c0, c1);
        *(float2*)&L[(m0 + g + 8) * LROW + col] = make_float2(c2, c3);
    }
    __syncthreads();

    if (t < M_CTA) {
        const int n = blk_tok + t;
        if (n < n_tokens) {
            float p[N_EXP];
            const float* Lr = L + t * LROW;
#pragma unroll
            for (int e = 0; e < N_EXP; e++) p[e] = Lr[e];

            float m = p[0];
#pragma unroll
            for (int e = 1; e < N_EXP; e++) m = fmaxf(m, p[e]);
            float ssum = 0.f;
#pragma unroll
            for (int e = 0; e < N_EXP; e++) { p[e] = expf(p[e] - m); ssum += p[e]; }
            float inv = 1.0f / ssum;
#pragma unroll
            for (int e = 0; e < N_EXP; e++) p[e] *= inv;

            const long long NK   = (long long)n_tokens * TOPK;
            const long long full = 2 * NK + (long long)n_tokens * N_EXP;

            if (out_size >= full) {
                float* pout = out + 2 * NK + (size_t)n * N_EXP;
#pragma unroll
                for (int e = 0; e < N_EXP; e++) pout[e] = p[e];
            }

            float tv[TOPK];
            int   ti[TOPK];
#pragma unroll
            for (int k = 0; k < TOPK; k++) { tv[k] = -1.0f; ti[k] = 0; }
#pragma unroll
            for (int e = 0; e < N_EXP; e++) {
                float v = p[e];
                if (v > tv[TOPK - 1]) {
                    tv[TOPK - 1] = v;
                    ti[TOPK - 1] = e;
#pragma unroll
                    for (int j = TOPK - 1; j > 0; j--) {
                        if (tv[j] > tv[j - 1]) {
                            float tf = tv[j]; tv[j] = tv[j - 1]; tv[j - 1] = tf;
                            int   tn = ti[j]; ti[j] = ti[j - 1]; ti[j - 1] = tn;
                        }
                    }
                }
            }
            float ws2 = 0.f;
#pragma unroll
            for (int k = 0; k < TOPK; k++) ws2 += tv[k];
            float winv = 1.0f / (ws2 + 1e-9f);

            if (out_size >= 2 * NK) {
#pragma unroll
                for (int k = 0; k < TOPK; k++) {
                    out[(size_t)n * TOPK + k]      = (float)ti[k];
                    out[NK + (size_t)n * TOPK + k] = tv[k] * winv;
                }
            } else if (out_size >= NK) {
#pragma unroll
                for (int k = 0; k < TOPK; k++)
                    out[(size_t)n * TOPK + k] = (float)ti[k];
            }
        }
    }
}

extern "C" void kernel_launch(void* const* d_in, const int* in_sizes, int n_in,
                              void* d_out, int out_size)
{
    const float* x = (const float*)d_in[0];
    const float* W = (const float*)d_in[1];
    int n_tokens = in_sizes[0] / D_MODEL;            // 16384

    split_W<<<(N_EXP * D_MODEL + 255) / 256, 256>>>(W);

    cudaFuncSetAttribute(router_kernel,
                         cudaFuncAttributeMaxDynamicSharedMemorySize, SMEMB);
    int grid = (n_tokens + M_CTA - 1) / M_CTA;       // 256
    router_kernel<<<grid, TPB, SMEMB>>>(x, (float*)d_out, n_tokens,
                                        (long long)out_size);
}